// round 2
// baseline (speedup 1.0000x reference)
#include <cuda_runtime.h>
#include <cuda_bf16.h>

// Problem constants
#define B_     32
#define CIN    64
#define H_     64
#define W_     64
#define COUT   128
#define CONN   4
#define KHW    9          // KH*KW
#define RROWS  4          // output rows per block stripe
#define SROWS  (RROWS+2)  // shared rows incl. halo (di in 0..2, pad_l=1)
#define NTHREADS 512
#define NSTRIPES (H_ / RROWS)   // 16

// Shared memory layout (bytes)
#define XS_FLOATS (CIN * SROWS * W_)        // 64*6*64 = 24576
#define XS_BYTES  (XS_FLOATS * 4)           // 98304
#define TBL_OFF   (XS_BYTES)                // uint4[512] packed (offs,dj,w,pad): 8192 B
#define BSH_OFF   (TBL_OFF + 8192)          // float[128] : 512 B
#define SMEM_TOTAL (BSH_OFF + 512)          // 107008 B

__global__ void __launch_bounds__(NTHREADS, 2)
lp_conv2d_bt_kernel(const float* __restrict__ x,
                    const float* __restrict__ wts,
                    const float* __restrict__ bias,
                    const int*   __restrict__ conn,
                    float* __restrict__ out)
{
    extern __shared__ char smem[];
    float* xs  = (float*)smem;
    uint4* tbl = (uint4*)(smem + TBL_OFF);
    float* bsh = (float*)(smem + BSH_OFF);

    const int tid = threadIdx.x;
    const int s   = blockIdx.x;   // stripe index 0..15
    const int b   = blockIdx.y;   // batch 0..31

    // ---- Stage conn tables: 512 (o,j) entries, one per thread ----
    {
        int idx = conn[tid];               // 0 .. CIN*KHW-1
        int c   = idx / KHW;               // input channel
        int rem = idx - c * KHW;
        int di  = rem / 3;
        int dj  = rem - di * 3;
        uint4 t;
        t.x = (unsigned)(c * (SROWS * W_) + di * W_);  // float offset into xs
        t.y = (unsigned)dj;
        t.z = __float_as_uint(wts[tid]);
        t.w = 0u;
        tbl[tid] = t;
        if (tid < COUT) bsh[tid] = bias[tid];
    }

    // ---- Load input stripe: all 64 channels, SROWS rows (edge-clamped), 64 cols ----
    const int i0 = s * RROWS;
    const float4* __restrict__ xsrc =
        (const float4*)(x + (size_t)b * (CIN * H_ * W_));
    // total float4s: CIN * SROWS * (W_/4) = 6144 ; 12 per thread
    float4* xs4 = (float4*)xs;
    #pragma unroll
    for (int it = 0; it < (CIN * SROWS * (W_/4)) / NTHREADS; it++) {
        int idx = tid + it * NTHREADS;
        int ch  = idx / (SROWS * (W_/4));          // /96
        int rem = idx - ch * (SROWS * (W_/4));
        int r   = rem / (W_/4);
        int c4  = rem - r * (W_/4);
        int gr  = i0 - 1 + r;                      // global row with halo
        gr = max(0, min(H_ - 1, gr));              // edge padding = clamp
        xs4[(ch * SROWS + r) * (W_/4) + c4] = xsrc[(ch * H_ + gr) * (W_/4) + c4];
    }
    __syncthreads();

    // ---- Compute: lane = column, slot picks o-subset ----
    const int col  = tid & 63;     // 0..63 (warp lanes -> consecutive cols within warp)
    const int slot = tid >> 6;     // 0..7

    float* outbase = out + (((size_t)b * COUT) * H_ + i0) * W_ + col;

    #pragma unroll 4
    for (int k = 0; k < 16; k++) {
        const int o = slot * 16 + k;             // 0..127, all distinct across slots
        float m0 = 0.0f, m1 = 0.0f, m2 = 0.0f, m3 = 0.0f;  // |diff|>=0 -> 0-init safe
        #pragma unroll
        for (int j = 0; j < CONN; j++) {
            const uint4 t = tbl[o * CONN + j];   // broadcast LDS.128
            const float w = __uint_as_float(t.z);
            int cl = col + (int)t.y - 1;
            cl = max(0, min(W_ - 1, cl));        // edge padding = clamp
            const float* p = xs + t.x + cl;      // row (ri+di) via t.x + p[ri*W_]
            m0 = fmaxf(m0, fabsf(w - p[0 * W_]));
            m1 = fmaxf(m1, fabsf(w - p[1 * W_]));
            m2 = fmaxf(m2, fabsf(w - p[2 * W_]));
            m3 = fmaxf(m3, fabsf(w - p[3 * W_]));
        }
        const float bv = bsh[o];
        float* po = outbase + (size_t)o * (H_ * W_);
        po[0 * W_] = m0 + bv;
        po[1 * W_] = m1 + bv;
        po[2 * W_] = m2 + bv;
        po[3 * W_] = m3 + bv;
    }
}

extern "C" void kernel_launch(void* const* d_in, const int* in_sizes, int n_in,
                              void* d_out, int out_size)
{
    const float* x    = (const float*)d_in[0];   // [32,64,64,64]
    const float* wts  = (const float*)d_in[1];   // [128,4]
    const float* bias = (const float*)d_in[2];   // [128,1,1]
    const int*   conn = (const int*)d_in[3];     // [128,4] int32
    float* out = (float*)d_out;                  // [32,128,64,64]

    static_assert(SMEM_TOTAL <= 227 * 1024, "smem");
    cudaFuncSetAttribute(lp_conv2d_bt_kernel,
                         cudaFuncAttributeMaxDynamicSharedMemorySize, SMEM_TOTAL);

    dim3 grid(NSTRIPES, B_);
    lp_conv2d_bt_kernel<<<grid, NTHREADS, SMEM_TOTAL>>>(x, wts, bias, conn, out);
}